// round 16
// baseline (speedup 1.0000x reference)
#include <cuda_runtime.h>
#include <cuda_fp16.h>

#define NCAM 6
#define CCH  128
#define H0   32
#define W0   88
#define H1   16
#define W1   44
#define H0P  (H0+2)       // 34
#define W0P  (W0+2)       // 90
#define H1P  (H1+2)       // 18
#define W1P  (W1+2)       // 46
#define HW0  (H0*W0)      // 2816
#define HW1  (H1*W1)      // 704
#define QDIM 16384
#define PPTS 4
#define NTASK (QDIM * PPTS)
#define EPSF 1e-5f
#define FULLMASK 0xffffffffu

// Transposed + zero-padded FP16 feature cache: [N, H+2, W+2, C].
// Borders never written; __device__ globals zero-init => out-of-range
// bilinear corners read exact zeros (padding_mode='zeros').
__device__ __half g_f0t[NCAM * H0P * W0P * CCH];   // ~4.7 MB
__device__ __half g_f1t[NCAM * H1P * W1P * CCH];   // ~1.25 MB

// -------------------------------------------------------------------------
// Fat-tile transpose + fp32->fp16: one block = full C=128 x 32-hw strip.
// -------------------------------------------------------------------------
#define NSTRIP0 (HW0 / 32)    // 88
#define NSTRIP1 (HW1 / 32)    // 22
#define NBLKT0  (NCAM * NSTRIP0)   // 528
#define NBLKT1  (NCAM * NSTRIP1)   // 132

__global__ void __launch_bounds__(256)
transpose_feats_kernel(const float* __restrict__ f0,
                       const float* __restrict__ f1) {
    __shared__ float tile[128][33];

    int b = blockIdx.x;
    const float* __restrict__ src;
    __half* __restrict__ dst;
    int n, strip, HW, W, WP;
    size_t HPWP;
    if (b < NBLKT0) {
        n = b / NSTRIP0; strip = b % NSTRIP0;
        src = f0; dst = g_f0t; HW = HW0; W = W0; WP = W0P;
        HPWP = (size_t)H0P * W0P;
    } else {
        b -= NBLKT0;
        n = b / NSTRIP1; strip = b % NSTRIP1;
        src = f1; dst = g_f1t; HW = HW1; W = W1; WP = W1P;
        HPWP = (size_t)H1P * W1P;
    }

    int t = threadIdx.x;
    {
        int col4 = (t & 7) * 4;
        const float* sp = src + (size_t)n * CCH * HW + strip * 32 + col4;
#pragma unroll
        for (int i = 0; i < 4; i++) {
            int c = (t >> 3) + 32 * i;
            float4 v = *reinterpret_cast<const float4*>(sp + (size_t)c * HW);
            tile[c][col4 + 0] = v.x;
            tile[c][col4 + 1] = v.y;
            tile[c][col4 + 2] = v.z;
            tile[c][col4 + 3] = v.w;
        }
    }
    __syncthreads();

    {
        int hw    = t >> 3;
        int cbase = (t & 7) * 16;
        int hwglob = strip * 32 + hw;
        int h = hwglob / W;
        int w = hwglob - h * W;
        __half* dp = dst + ((size_t)n * HPWP + (size_t)(h + 1) * WP + (w + 1)) * CCH
                   + cbase;
        uint4 s0, s1;
        unsigned* su = reinterpret_cast<unsigned*>(&s0);
#pragma unroll
        for (int k = 0; k < 4; k++) {
            __half2 hv = __floats2half2_rn(tile[cbase + 2*k][hw],
                                           tile[cbase + 2*k + 1][hw]);
            memcpy(su + k, &hv, 4);
        }
        unsigned* su1 = reinterpret_cast<unsigned*>(&s1);
#pragma unroll
        for (int k = 0; k < 4; k++) {
            __half2 hv = __floats2half2_rn(tile[cbase + 8 + 2*k][hw],
                                           tile[cbase + 9 + 2*k][hw]);
            memcpy(su1 + k, &hv, 4);
        }
        *reinterpret_cast<uint4*>(dp)     = s0;
        *reinterpret_cast<uint4*>(dp + 8) = s1;
    }
}

// -------------------------------------------------------------------------
// Main sampling kernel: 2 tasks/warp; fp16 HFMA2 bilinear blend per
// cam-level, fp32 accumulation across cameras.
// -------------------------------------------------------------------------

struct AccF { float x, y, z, w; };

__device__ __forceinline__ void corner(const char* __restrict__ base, int byteoff,
                                       __half2 w2, __half2& a01, __half2& a23) {
    uint2 h = *reinterpret_cast<const uint2*>(base + byteoff);   // 4 halfs
    __half2 h01, h23;
    memcpy(&h01, &h.x, 4);
    memcpy(&h23, &h.y, 4);
    a01 = __hfma2(h01, w2, a01);
    a23 = __hfma2(h23, w2, a23);
}

// Clamp-free bilinear sample of one padded fp16 level; u,v warp-uniform.
// 4-corner blend in fp16 (HFMA2), result accumulated in fp32.
__device__ __forceinline__ void sample_level(const char* __restrict__ base,
                                             float u, float v, int cambase,
                                             int Wl, int Hl, int WP,
                                             AccF& a) {
    float px = fmaf(u, (float)Wl, 0.5f);
    float py = fmaf(v, (float)Hl, 0.5f);
    int x0 = __float2int_rd(px);
    int y0 = __float2int_rd(py);
    float wx1 = px - __int2float_rn(x0);
    float wy1 = py - __int2float_rn(y0);
    float wx0 = 1.0f - wx1;
    float wy0 = 1.0f - wy1;

    __half2 w00 = __float2half2_rn(wx0 * wy0);
    __half2 w01 = __float2half2_rn(wx1 * wy0);
    __half2 w10 = __float2half2_rn(wx0 * wy1);
    __half2 w11 = __float2half2_rn(wx1 * wy1);

    int o00 = (cambase + y0 * WP + x0) << 8;   // *CCH*2 bytes
    int rowB = WP << 8;

    __half2 a01 = __float2half2_rn(0.f);
    __half2 a23 = __float2half2_rn(0.f);
    corner(base, o00,              w00, a01, a23);
    corner(base, o00 + 256,        w01, a01, a23);
    corner(base, o00 + rowB,       w10, a01, a23);
    corner(base, o00 + rowB + 256, w11, a01, a23);

    float2 f01 = __half22float2(a01);
    float2 f23 = __half22float2(a23);
    a.x += f01.x;
    a.y += f01.y;
    a.z += f23.x;
    a.w += f23.y;
}

__global__ void __launch_bounds__(256, 8)
bev_sample_kernel(const float* __restrict__ refpts,
                  const float* __restrict__ lidar2img,
                  float* __restrict__ out) {
    __shared__ float sM[NCAM * 16];
    if (threadIdx.x < NCAM * 16) sM[threadIdx.x] = lidar2img[threadIdx.x];
    __syncthreads();

    int wpair = blockIdx.x * 8 + (threadIdx.x >> 5);
    int lane  = threadIdx.x & 31;
    int t0 = wpair * 2;
    int which = (lane >> 3) & 1;
    int cam   = lane & 7;
    int task  = t0 + which;

    // Projection: lanes 0-5 -> task A, lanes 8-13 -> task B.
    bool valid = false;
    float u = 0.f, v = 0.f;
    if (lane < 16 && cam < NCAM) {
        int q = task >> 2;
        int p = task & 3;
        int hb = q >> 7;
        int wb = q & 127;
        const float* rp = refpts + ((size_t)((p * 128 + hb) * 128 + wb)) * 3;
        float X = __ldg(rp + 0) * 102.4f - 51.2f;
        float Y = __ldg(rp + 1) * 102.4f - 51.2f;
        float Z = __ldg(rp + 2) * 8.0f  - 5.0f;

        const float* M = sM + cam * 16;
        float cz = fmaf(M[8], X, fmaf(M[9], Y, fmaf(M[10], Z, M[11])));
        if (cz > EPSF) {
            float cx = fmaf(M[0], X, fmaf(M[1], Y, fmaf(M[2], Z, M[3])));
            float cy = fmaf(M[4], X, fmaf(M[5], Y, fmaf(M[6], Z, M[7])));
            float invz = __fdividef(1.0f, cz);
            u = cx * invz * (1.0f / 704.0f);
            v = cy * invz * (1.0f / 256.0f);
            valid = (u > 0.0f) & (u < 1.0f) & (v > 0.0f) & (v < 1.0f);
        }
    }

    unsigned vm  = __ballot_sync(FULLMASK, valid);
    unsigned vmA = vm & 0x3Fu;
    unsigned vmB = (vm >> 8) & 0x3Fu;

    const char* b0 = (const char*)g_f0t + lane * 8;   // lane channel offset
    const char* b1 = (const char*)g_f1t + lane * 8;

    // ---------------- Task A ----------------
    {
        AccF a = {0.f, 0.f, 0.f, 0.f};
        int cnt = __popc(vmA);
#pragma unroll
        for (int c = 0; c < NCAM; c++) {
            if (vmA & (1u << c)) {
                float uu = __shfl_sync(FULLMASK, u, c);
                float vv = __shfl_sync(FULLMASK, v, c);
                sample_level(b0, uu, vv, c * (H0P * W0P), W0, H0, W0P, a);
                sample_level(b1, uu, vv, c * (H1P * W1P), W1, H1, W1P, a);
            }
        }
        float scale = 0.5f / fmaxf((float)cnt, 1.0f);
        float4 o;
        o.x = a.x * scale; o.y = a.y * scale;
        o.z = a.z * scale; o.w = a.w * scale;
        *reinterpret_cast<float4*>(out + (size_t)t0 * CCH + lane * 4) = o;
    }

    // ---------------- Task B ----------------
    {
        AccF a = {0.f, 0.f, 0.f, 0.f};
        int cnt = __popc(vmB);
#pragma unroll
        for (int c = 0; c < NCAM; c++) {
            if (vmB & (1u << c)) {
                float uu = __shfl_sync(FULLMASK, u, c + 8);
                float vv = __shfl_sync(FULLMASK, v, c + 8);
                sample_level(b0, uu, vv, c * (H0P * W0P), W0, H0, W0P, a);
                sample_level(b1, uu, vv, c * (H1P * W1P), W1, H1, W1P, a);
            }
        }
        float scale = 0.5f / fmaxf((float)cnt, 1.0f);
        float4 o;
        o.x = a.x * scale; o.y = a.y * scale;
        o.z = a.z * scale; o.w = a.w * scale;
        *reinterpret_cast<float4*>(out + (size_t)(t0 + 1) * CCH + lane * 4) = o;
    }
}

extern "C" void kernel_launch(void* const* d_in, const int* in_sizes, int n_in,
                              void* d_out, int out_size) {
    const float* refpts    = (const float*)d_in[0];   // [1,4,128,128,3]
    const float* feats0    = (const float*)d_in[1];   // [1,6,128,32,88]
    const float* feats1    = (const float*)d_in[2];   // [1,6,128,16,44]
    const float* lidar2img = (const float*)d_in[3];   // [1,6,4,4]
    float* out = (float*)d_out;                       // [1,16384,4,128]

    transpose_feats_kernel<<<NBLKT0 + NBLKT1, 256>>>(feats0, feats1);
    // 2 tasks per warp, 8 warps per block -> 4096 blocks.
    bev_sample_kernel<<<NTASK / 16, 256>>>(refpts, lidar2img, out);
}

// round 17
// speedup vs baseline: 1.0811x; 1.0811x over previous
#include <cuda_runtime.h>
#include <cuda_fp16.h>

#define NCAM 6
#define CCH  128
#define H0   32
#define W0   88
#define H1   16
#define W1   44
#define H0P  (H0+2)       // 34
#define W0P  (W0+2)       // 90
#define H1P  (H1+2)       // 18
#define W1P  (W1+2)       // 46
#define HW0  (H0*W0)      // 2816
#define HW1  (H1*W1)      // 704
#define QDIM 16384
#define PPTS 4
#define NTASK (QDIM * PPTS)
#define EPSF 1e-5f
#define FULLMASK 0xffffffffu

// Transposed + zero-padded FP16 feature cache: [N, H+2, W+2, C].
// Borders never written; __device__ globals zero-init => out-of-range
// bilinear corners read exact zeros (padding_mode='zeros').
__device__ __half g_f0t[NCAM * H0P * W0P * CCH];   // ~4.7 MB
__device__ __half g_f1t[NCAM * H1P * W1P * CCH];   // ~1.25 MB

// -------------------------------------------------------------------------
// Fat-tile transpose + fp32->fp16: one block = full C=128 x 32-hw strip.
// -------------------------------------------------------------------------
#define NSTRIP0 (HW0 / 32)    // 88
#define NSTRIP1 (HW1 / 32)    // 22
#define NBLKT0  (NCAM * NSTRIP0)   // 528
#define NBLKT1  (NCAM * NSTRIP1)   // 132

__global__ void __launch_bounds__(256)
transpose_feats_kernel(const float* __restrict__ f0,
                       const float* __restrict__ f1) {
    __shared__ float tile[128][33];

    int b = blockIdx.x;
    const float* __restrict__ src;
    __half* __restrict__ dst;
    int n, strip, HW, W, WP;
    size_t HPWP;
    if (b < NBLKT0) {
        n = b / NSTRIP0; strip = b % NSTRIP0;
        src = f0; dst = g_f0t; HW = HW0; W = W0; WP = W0P;
        HPWP = (size_t)H0P * W0P;
    } else {
        b -= NBLKT0;
        n = b / NSTRIP1; strip = b % NSTRIP1;
        src = f1; dst = g_f1t; HW = HW1; W = W1; WP = W1P;
        HPWP = (size_t)H1P * W1P;
    }

    int t = threadIdx.x;
    {
        int col4 = (t & 7) * 4;
        const float* sp = src + (size_t)n * CCH * HW + strip * 32 + col4;
#pragma unroll
        for (int i = 0; i < 4; i++) {
            int c = (t >> 3) + 32 * i;
            float4 v = *reinterpret_cast<const float4*>(sp + (size_t)c * HW);
            tile[c][col4 + 0] = v.x;
            tile[c][col4 + 1] = v.y;
            tile[c][col4 + 2] = v.z;
            tile[c][col4 + 3] = v.w;
        }
    }
    __syncthreads();

    {
        int hw    = t >> 3;
        int cbase = (t & 7) * 16;
        int hwglob = strip * 32 + hw;
        int h = hwglob / W;
        int w = hwglob - h * W;
        __half* dp = dst + ((size_t)n * HPWP + (size_t)(h + 1) * WP + (w + 1)) * CCH
                   + cbase;
        uint4 s0, s1;
        unsigned* su = reinterpret_cast<unsigned*>(&s0);
#pragma unroll
        for (int k = 0; k < 4; k++) {
            __half2 hv = __floats2half2_rn(tile[cbase + 2*k][hw],
                                           tile[cbase + 2*k + 1][hw]);
            memcpy(su + k, &hv, 4);
        }
        unsigned* su1 = reinterpret_cast<unsigned*>(&s1);
#pragma unroll
        for (int k = 0; k < 4; k++) {
            __half2 hv = __floats2half2_rn(tile[cbase + 8 + 2*k][hw],
                                           tile[cbase + 9 + 2*k][hw]);
            memcpy(su1 + k, &hv, 4);
        }
        *reinterpret_cast<uint4*>(dp)     = s0;
        *reinterpret_cast<uint4*>(dp + 8) = s1;
    }

#if __CUDA_ARCH__ >= 900
    cudaTriggerProgrammaticLaunchCompletion();
#endif
}

// -------------------------------------------------------------------------
// Main sampling kernel: 2 tasks/warp; fp16 HFMA2 blend across BOTH levels
// per cam (8 corners), single fp32 convert+add per cam.
// -------------------------------------------------------------------------

struct AccF { float x, y, z, w; };

__device__ __forceinline__ void corner(const char* __restrict__ base, int byteoff,
                                       __half2 w2, __half2& a01, __half2& a23) {
    uint2 h = *reinterpret_cast<const uint2*>(base + byteoff);   // 4 halfs
    __half2 h01, h23;
    memcpy(&h01, &h.x, 4);
    memcpy(&h23, &h.y, 4);
    a01 = __hfma2(h01, w2, a01);
    a23 = __hfma2(h23, w2, a23);
}

// Clamp-free bilinear sample of one padded fp16 level into fp16 accumulators.
__device__ __forceinline__ void sample_level_h(const char* __restrict__ base,
                                               float u, float v, int cambase,
                                               int Wl, int Hl, int WP,
                                               __half2& a01, __half2& a23) {
    float px = fmaf(u, (float)Wl, 0.5f);
    float py = fmaf(v, (float)Hl, 0.5f);
    int x0 = __float2int_rd(px);
    int y0 = __float2int_rd(py);
    float wx1 = px - __int2float_rn(x0);
    float wy1 = py - __int2float_rn(y0);
    float wx0 = 1.0f - wx1;
    float wy0 = 1.0f - wy1;

    __half2 w00 = __float2half2_rn(wx0 * wy0);
    __half2 w01 = __float2half2_rn(wx1 * wy0);
    __half2 w10 = __float2half2_rn(wx0 * wy1);
    __half2 w11 = __float2half2_rn(wx1 * wy1);

    int o00 = (cambase + y0 * WP + x0) << 8;   // *CCH*2 bytes
    int rowB = WP << 8;
    corner(base, o00,              w00, a01, a23);
    corner(base, o00 + 256,        w01, a01, a23);
    corner(base, o00 + rowB,       w10, a01, a23);
    corner(base, o00 + rowB + 256, w11, a01, a23);
}

__global__ void __launch_bounds__(256, 8)
bev_sample_kernel(const float* __restrict__ refpts,
                  const float* __restrict__ lidar2img,
                  float* __restrict__ out) {
    __shared__ float sM[NCAM * 16];
    if (threadIdx.x < NCAM * 16) sM[threadIdx.x] = lidar2img[threadIdx.x];
    __syncthreads();

    int wpair = blockIdx.x * 8 + (threadIdx.x >> 5);
    int lane  = threadIdx.x & 31;
    int t0 = wpair * 2;
    int which = (lane >> 3) & 1;
    int cam   = lane & 7;
    int task  = t0 + which;

    // Projection: lanes 0-5 -> task A, lanes 8-13 -> task B.
    // (Independent of the transpose output — runs before griddep sync.)
    bool valid = false;
    float u = 0.f, v = 0.f;
    if (lane < 16 && cam < NCAM) {
        int q = task >> 2;
        int p = task & 3;
        int hb = q >> 7;
        int wb = q & 127;
        const float* rp = refpts + ((size_t)((p * 128 + hb) * 128 + wb)) * 3;
        float X = __ldg(rp + 0) * 102.4f - 51.2f;
        float Y = __ldg(rp + 1) * 102.4f - 51.2f;
        float Z = __ldg(rp + 2) * 8.0f  - 5.0f;

        const float* M = sM + cam * 16;
        float cz = fmaf(M[8], X, fmaf(M[9], Y, fmaf(M[10], Z, M[11])));
        if (cz > EPSF) {
            float cx = fmaf(M[0], X, fmaf(M[1], Y, fmaf(M[2], Z, M[3])));
            float cy = fmaf(M[4], X, fmaf(M[5], Y, fmaf(M[6], Z, M[7])));
            float invz = __fdividef(1.0f, cz);
            u = cx * invz * (1.0f / 704.0f);
            v = cy * invz * (1.0f / 256.0f);
            valid = (u > 0.0f) & (u < 1.0f) & (v > 0.0f) & (v < 1.0f);
        }
    }

    unsigned vm  = __ballot_sync(FULLMASK, valid);
    unsigned vmA = vm & 0x3Fu;
    unsigned vmB = (vm >> 8) & 0x3Fu;

#if __CUDA_ARCH__ >= 900
    cudaGridDependencySynchronize();   // transpose results needed from here
#endif

    const char* b0 = (const char*)g_f0t + lane * 8;   // lane channel offset
    const char* b1 = (const char*)g_f1t + lane * 8;

    // ---------------- Task A ----------------
    {
        AccF a = {0.f, 0.f, 0.f, 0.f};
        int cnt = __popc(vmA);
#pragma unroll
        for (int c = 0; c < NCAM; c++) {
            if (vmA & (1u << c)) {
                float uu = __shfl_sync(FULLMASK, u, c);
                float vv = __shfl_sync(FULLMASK, v, c);
                __half2 a01 = __float2half2_rn(0.f);
                __half2 a23 = __float2half2_rn(0.f);
                sample_level_h(b0, uu, vv, c * (H0P * W0P), W0, H0, W0P, a01, a23);
                sample_level_h(b1, uu, vv, c * (H1P * W1P), W1, H1, W1P, a01, a23);
                float2 f01 = __half22float2(a01);
                float2 f23 = __half22float2(a23);
                a.x += f01.x; a.y += f01.y;
                a.z += f23.x; a.w += f23.y;
            }
        }
        float scale = 0.5f / fmaxf((float)cnt, 1.0f);
        float4 o;
        o.x = a.x * scale; o.y = a.y * scale;
        o.z = a.z * scale; o.w = a.w * scale;
        *reinterpret_cast<float4*>(out + (size_t)t0 * CCH + lane * 4) = o;
    }

    // ---------------- Task B ----------------
    {
        AccF a = {0.f, 0.f, 0.f, 0.f};
        int cnt = __popc(vmB);
#pragma unroll
        for (int c = 0; c < NCAM; c++) {
            if (vmB & (1u << c)) {
                float uu = __shfl_sync(FULLMASK, u, c + 8);
                float vv = __shfl_sync(FULLMASK, v, c + 8);
                __half2 a01 = __float2half2_rn(0.f);
                __half2 a23 = __float2half2_rn(0.f);
                sample_level_h(b0, uu, vv, c * (H0P * W0P), W0, H0, W0P, a01, a23);
                sample_level_h(b1, uu, vv, c * (H1P * W1P), W1, H1, W1P, a01, a23);
                float2 f01 = __half22float2(a01);
                float2 f23 = __half22float2(a23);
                a.x += f01.x; a.y += f01.y;
                a.z += f23.x; a.w += f23.y;
            }
        }
        float scale = 0.5f / fmaxf((float)cnt, 1.0f);
        float4 o;
        o.x = a.x * scale; o.y = a.y * scale;
        o.z = a.z * scale; o.w = a.w * scale;
        *reinterpret_cast<float4*>(out + (size_t)(t0 + 1) * CCH + lane * 4) = o;
    }
}

extern "C" void kernel_launch(void* const* d_in, const int* in_sizes, int n_in,
                              void* d_out, int out_size) {
    const float* refpts    = (const float*)d_in[0];   // [1,4,128,128,3]
    const float* feats0    = (const float*)d_in[1];   // [1,6,128,32,88]
    const float* feats1    = (const float*)d_in[2];   // [1,6,128,16,44]
    const float* lidar2img = (const float*)d_in[3];   // [1,6,4,4]
    float* out = (float*)d_out;                       // [1,16384,4,128]

    transpose_feats_kernel<<<NBLKT0 + NBLKT1, 256>>>(feats0, feats1);

    // Programmatic dependent launch: let the sampler's prologue overlap the
    // transpose tail. cudaGridDependencySynchronize() in-kernel guards the
    // actual dependency; if PDL is unsupported this degrades to a normal
    // serialized launch.
    cudaLaunchConfig_t cfg = {};
    cfg.gridDim  = dim3(NTASK / 16, 1, 1);
    cfg.blockDim = dim3(256, 1, 1);
    cudaLaunchAttribute attrs[1];
    attrs[0].id = cudaLaunchAttributeProgrammaticStreamSerialization;
    attrs[0].val.programmaticStreamSerializationAllowed = 1;
    cfg.attrs = attrs;
    cfg.numAttrs = 1;
    cudaLaunchKernelEx(&cfg, bev_sample_kernel, refpts, lidar2img, (float*)out);
}